// round 5
// baseline (speedup 1.0000x reference)
#include <cuda_runtime.h>
#include <stdint.h>

#define NPART_MAX 100000
#define CUTOFF 0.9f
#define PREFAC 138.93544539709032f

// Packed per-particle record: 32 bytes = exactly one L2 sector.
// g_pack[2*i+0] = {x, y, z, q * sqrt(PREFAC)}
// g_pack[2*i+1] = {sigma, epsilon, 0, 0}
__device__ __align__(32) float4 g_pack[2 * NPART_MAX];

__global__ void pack_kernel(const float* __restrict__ coords,
                            const float* __restrict__ charges,
                            const float* __restrict__ sigma,
                            const float* __restrict__ epsilon,
                            float* __restrict__ out,
                            int n)
{
    int i = blockIdx.x * blockDim.x + threadIdx.x;
    if (i == 0) out[0] = 0.0f;   // d_out is poisoned to 0xAA; zero it here.
    if (i < n) {
        float x = coords[3 * i + 0];
        float y = coords[3 * i + 1];
        float z = coords[3 * i + 2];
        float qs = charges[i] * sqrtf(PREFAC);
        g_pack[2 * i + 0] = make_float4(x, y, z, qs);
        g_pack[2 * i + 1] = make_float4(sigma[i], epsilon[i], 0.0f, 0.0f);
    }
}

__device__ __forceinline__ float pair_energy(int i, int j,
                                             float Lx, float Ly, float Lz,
                                             float iLx, float iLy, float iLz,
                                             float cut2)
{
    // inter-molecular check (i/3 != j/3) subsumes i != j
    if (i / 3 == j / 3) return 0.0f;

    float4 a = g_pack[2 * i];
    float4 b = g_pack[2 * j];

    float dx = a.x - b.x;
    float dy = a.y - b.y;
    float dz = a.z - b.z;
    dx -= Lx * rintf(dx * iLx);
    dy -= Ly * rintf(dy * iLy);
    dz -= Lz * rintf(dz * iLz);
    float r2 = dx * dx + dy * dy + dz * dz;

    if (r2 >= cut2) return 0.0f;   // ~99.7% of pairs exit here

    float4 sa = g_pack[2 * i + 1];   // second half of the same 32B record -> L1 hit
    float4 sb = g_pack[2 * j + 1];

    float inv_r  = rsqrtf(r2);
    float inv_r2 = inv_r * inv_r;

    float e_coul = a.w * b.w * inv_r;      // PREFAC folded into charges

    float sig = 0.5f * (sa.x + sb.x);
    float eps = sqrtf(sa.y * sb.y);
    float sr2 = sig * sig * inv_r2;
    float sr6 = sr2 * sr2 * sr2;
    float e_lj = 4.0f * eps * (sr6 * sr6 - sr6);

    return e_coul + e_lj;
}

__global__ void energy_kernel(const int4* __restrict__ pairs4,  // 2 pairs per int4
                              int n4,                            // number of int4s
                              const int2* __restrict__ pairs2,   // tail handling
                              int npairs,
                              const float* __restrict__ box,
                              float* __restrict__ out)
{
    float Lx = __ldg(&box[0]), Ly = __ldg(&box[4]), Lz = __ldg(&box[8]);
    float iLx = __frcp_rn(Lx), iLy = __frcp_rn(Ly), iLz = __frcp_rn(Lz);
    const float cut2 = CUTOFF * CUTOFF;

    float acc = 0.0f;

    int tid    = blockIdx.x * blockDim.x + threadIdx.x;
    int stride = gridDim.x * blockDim.x;

    // Double-pumped: 2 int4 loads (4 pairs) in flight per iteration for MLP.
    int k = tid;
    for (; k + stride < n4; k += 2 * stride) {
        int4 p0 = pairs4[k];
        int4 p1 = pairs4[k + stride];
        acc += pair_energy(p0.x, p0.y, Lx, Ly, Lz, iLx, iLy, iLz, cut2);
        acc += pair_energy(p0.z, p0.w, Lx, Ly, Lz, iLx, iLy, iLz, cut2);
        acc += pair_energy(p1.x, p1.y, Lx, Ly, Lz, iLx, iLy, iLz, cut2);
        acc += pair_energy(p1.z, p1.w, Lx, Ly, Lz, iLx, iLy, iLz, cut2);
    }
    if (k < n4) {
        int4 p0 = pairs4[k];
        acc += pair_energy(p0.x, p0.y, Lx, Ly, Lz, iLx, iLy, iLz, cut2);
        acc += pair_energy(p0.z, p0.w, Lx, Ly, Lz, iLx, iLy, iLz, cut2);
    }
    // tail (npairs odd): exactly one thread in the whole grid handles it
    if (tid == 0 && (npairs & 1)) {
        int2 p = pairs2[npairs - 1];
        acc += pair_energy(p.x, p.y, Lx, Ly, Lz, iLx, iLy, iLz, cut2);
    }

    // warp reduce
    #pragma unroll
    for (int off = 16; off > 0; off >>= 1)
        acc += __shfl_xor_sync(0xFFFFFFFFu, acc, off);

    __shared__ float warp_sums[32];
    int lane = threadIdx.x & 31;
    int wid  = threadIdx.x >> 5;
    if (lane == 0) warp_sums[wid] = acc;
    __syncthreads();

    int nwarps = blockDim.x >> 5;
    if (wid == 0) {
        float v = (lane < nwarps) ? warp_sums[lane] : 0.0f;
        #pragma unroll
        for (int off = 16; off > 0; off >>= 1)
            v += __shfl_xor_sync(0xFFFFFFFFu, v, off);
        if (lane == 0) atomicAdd(out, v);
    }
}

extern "C" void kernel_launch(void* const* d_in, const int* in_sizes, int n_in,
                              void* d_out, int out_size)
{
    const float* coords  = (const float*)d_in[0];
    const float* box     = (const float*)d_in[1];
    const float* charges = (const float*)d_in[2];
    const float* sigma   = (const float*)d_in[3];
    const float* epsilon = (const float*)d_in[4];
    const int*   pairs   = (const int*)d_in[5];

    int n      = in_sizes[2];           // number of particles (charges count)
    int npairs = in_sizes[5] / 2;       // pairs is [NP, 2]

    float* out = (float*)d_out;

    // 1) pack particle data + zero output
    int pack_blocks = (n + 255) / 256;
    pack_kernel<<<pack_blocks, 256>>>(coords, charges, sigma, epsilon, out, n);

    // 2) energy reduction
    int n4 = npairs / 2;                // int4 = 2 pairs
    int threads = 256;
    int blocks = 148 * 16;              // grid-stride
    int max_blocks = (n4 + threads - 1) / threads;
    if (blocks > max_blocks) blocks = max_blocks > 0 ? max_blocks : 1;

    energy_kernel<<<blocks, threads>>>((const int4*)pairs, n4,
                                       (const int2*)pairs, npairs,
                                       box, out);
}